// round 13
// baseline (speedup 1.0000x reference)
#include <cuda_runtime.h>
#include <cstdint>

#define BB 8
#define SSL 1024
#define HH 8
#define DDIM 96
#define NKEY 7

__constant__ int c_dim[7]  = {1, 1, 2, 2, 2, 2, 2};
__constant__ int c_foff[7] = {0, 8, 16, 32, 48, 64, 80};
__constant__ int c_roff[7] = {0, 1, 2, 4, 6, 8, 10};

__device__ float g_Q[BB * HH * SSL * DDIM];
__device__ float g_K[BB * HH * SSL * DDIM];
__device__ float g_V[BB * HH * SSL * DDIM];
__device__ float g_O[BB * HH * SSL * DDIM];

__device__ __forceinline__ float tf32r(float x) {
    uint32_t u;
    asm("cvt.rna.tf32.f32 %0, %1;" : "=r"(u) : "f"(x));
    return __uint_as_float(u);
}

__device__ __forceinline__ void mma_tf32(float* c, const uint32_t* a,
                                         uint32_t b0, uint32_t b1) {
    asm volatile(
        "mma.sync.aligned.m16n8k8.row.col.f32.tf32.tf32.f32 "
        "{%0,%1,%2,%3}, {%4,%5,%6,%7}, {%8,%9}, {%0,%1,%2,%3};"
        : "+f"(c[0]), "+f"(c[1]), "+f"(c[2]), "+f"(c[3])
        : "r"(a[0]), "r"(a[1]), "r"(a[2]), "r"(a[3]), "r"(b0), "r"(b1));
}

__device__ __forceinline__ void ldsm_x4(uint32_t& r0, uint32_t& r1,
                                        uint32_t& r2, uint32_t& r3, uint32_t addr) {
    asm volatile("ldmatrix.sync.aligned.m8n8.x4.shared.b16 {%0,%1,%2,%3}, [%4];"
        : "=r"(r0), "=r"(r1), "=r"(r2), "=r"(r3) : "r"(addr));
}
__device__ __forceinline__ void ldsm_x2(uint32_t& r0, uint32_t& r1, uint32_t addr) {
    asm volatile("ldmatrix.sync.aligned.m8n8.x2.shared.b16 {%0,%1}, [%2];"
        : "=r"(r0), "=r"(r1) : "r"(addr));
}

__device__ __forceinline__ uint32_t s2u(const void* p) {
    return (uint32_t)__cvta_generic_to_shared(p);
}
__device__ __forceinline__ void cp_async16(uint32_t saddr, const void* g) {
    asm volatile("cp.async.cg.shared.global [%0], [%1], 16;" :: "r"(saddr), "l"(g));
}
#define CP_COMMIT() asm volatile("cp.async.commit_group;")

// ---------------------------------------------------------------------------
// Kernel 1: per-key, per-matrix QKV projection + head split, tf32 MMA
// NEW: smem-staged coalesced epilogue (32B-sector-aligned stores)
// ---------------------------------------------------------------------------
#define WPITCH 68
#define XPITCH 68
#define PROJ_SMEM_FLOATS (64 * WPITCH + 128 * XPITCH)

__global__ __launch_bounds__(256) void k_proj(
    const float* __restrict__ x0, const float* __restrict__ x1,
    const float* __restrict__ x2, const float* __restrict__ x3,
    const float* __restrict__ x4, const float* __restrict__ x5,
    const float* __restrict__ x6,
    const float* __restrict__ Wq, const float* __restrict__ Wk,
    const float* __restrict__ Wv)
{
    extern __shared__ float sm[];
    float* Ws = sm;                 // [64][68]
    float* xs = sm + 64 * WPITCH;   // [rows][68]; reused as output buffer

    const int key = blockIdx.z / 3;
    const int m3  = blockIdx.z % 3;
    const int b   = blockIdx.y;
    const int s0  = blockIdx.x * 64;
    const int d    = c_dim[key];
    const int rows = 64 * d;
    const int foff = c_foff[key];
    const int tid = threadIdx.x;

    const float* xg;
    switch (key) {
        case 0: xg = x0; break; case 1: xg = x1; break;
        case 2: xg = x2; break; case 3: xg = x3; break;
        case 4: xg = x4; break; case 5: xg = x5; break;
        default: xg = x6; break;
    }
    xg += (size_t)(b * SSL + s0) * d * 64;

    const float* wsrc = ((m3 == 0) ? Wq : (m3 == 1) ? Wk : Wv) + key * 4096;
    for (int i = tid; i < 4096; i += 256) {
        int o = i >> 6, k = i & 63;
        Ws[o * WPITCH + k] = tf32r(wsrc[i]);
    }
    for (int i = tid; i < rows * 64; i += 256) {
        int r = i >> 6, c = i & 63;
        xs[r * XPITCH + c] = tf32r(xg[i]);
    }
    __syncthreads();

    const int wid  = tid >> 5;
    const int lane = tid & 31;
    const int gid  = lane >> 2;
    const int tig  = lane & 3;
    const int rbase = (wid & 3) * 16 * d;
    const int cbase = (wid >> 2) * 32;

    float qacc[2][4][4];
    #pragma unroll
    for (int mf = 0; mf < 2; mf++)
        #pragma unroll
        for (int f = 0; f < 4; f++)
            #pragma unroll
            for (int c = 0; c < 4; c++) qacc[mf][f][c] = 0.0f;

    for (int k0 = 0; k0 < 64; k0 += 8) {
        uint32_t a[2][4];
        for (int mf = 0; mf < d; mf++) {
            const float* qb = xs + (rbase + mf * 16 + gid) * XPITCH + k0;
            a[mf][0] = __float_as_uint(qb[tig]);
            a[mf][1] = __float_as_uint(qb[8 * XPITCH + tig]);
            a[mf][2] = __float_as_uint(qb[tig + 4]);
            a[mf][3] = __float_as_uint(qb[8 * XPITCH + tig + 4]);
        }
        #pragma unroll
        for (int f = 0; f < 4; f++) {
            const float* kb = Ws + (cbase + f * 8 + gid) * WPITCH + k0;
            uint32_t b0 = __float_as_uint(kb[tig]);
            uint32_t b1 = __float_as_uint(kb[tig + 4]);
            mma_tf32(qacc[0][f], a[0], b0, b1);
            if (d == 2) mma_tf32(qacc[1][f], a[1], b0, b1);
        }
    }

    // ---- staged epilogue: frag -> smem (tf32-rounded), then coalesced out ----
    __syncthreads();   // xs fully consumed by MMA
    for (int mf = 0; mf < d; mf++) {
        int rlo = rbase + mf * 16 + gid;
        int rhi = rlo + 8;
        #pragma unroll
        for (int f = 0; f < 4; f++) {
            int col = cbase + f * 8 + tig * 2;
            xs[rlo * XPITCH + col]     = tf32r(qacc[mf][f][0]);
            xs[rlo * XPITCH + col + 1] = tf32r(qacc[mf][f][1]);
            xs[rhi * XPITCH + col]     = tf32r(qacc[mf][f][2]);
            xs[rhi * XPITCH + col + 1] = tf32r(qacc[mf][f][3]);
        }
    }
    __syncthreads();

    float* dst = (m3 == 0) ? g_Q : (m3 == 1) ? g_K : g_V;
    // i -> (row, h, half): write float4; per (h, s) a full 8d-float chunk
    for (int i = tid; i < rows * 16; i += 256) {
        int row = i >> 4, q4 = i & 15;
        int h = q4 >> 1, half = q4 & 1;
        int ss = row / d, dd = row - ss * d;
        float4 v = *(float4*)&xs[row * XPITCH + h * 8 + half * 4];
        *(float4*)(dst + (((size_t)(b * HH + h)) * SSL + s0 + ss) * DDIM
                   + foff + dd * 8 + half * 4) = v;
    }
}

// ---------------------------------------------------------------------------
// Kernel 2: flash attention (unchanged from R12): tf32 mma, fixed-max
// softmax, ldmatrix Q/K/P feeds, cp.async KV, 2 blocks/SM.
// ---------------------------------------------------------------------------
#define QT 64
#define KT 64
#define NTILES (SSL / KT)
#define QPITCH 100
#define KPITCH 100
#define VPITCH 104
#define PPITCH 68

#define ATTN_SMEM_FLOATS (QT*QPITCH + KT*KPITCH + KT*VPITCH + QT*PPITCH + 4*QT)

__global__ __launch_bounds__(256, 2) void k_attn()
{
    extern __shared__ float sm[];
    float* Qs    = sm;                      // [64][100]
    float* Ks    = Qs + QT * QPITCH;        // [64][100]
    float* Vs    = Ks + KT * KPITCH;        // [64][104]
    float* Ps    = Vs + KT * VPITCH;        // [64][68]
    float* red_s = Ps + QT * PPITCH;        // [4][64]

    const int bh = blockIdx.y;
    const int q0 = blockIdx.x * QT;
    const float* Qg = g_Q + ((size_t)bh * SSL + q0) * DDIM;
    const float* Kg = g_K + (size_t)bh * SSL * DDIM;
    const float* Vg = g_V + (size_t)bh * SSL * DDIM;

    const int tid  = threadIdx.x;
    const int wid  = tid >> 5;
    const int lane = tid & 31;
    const int gid  = lane >> 2;
    const int tig  = lane & 3;
    const int wy   = wid & 1;
    const int wx   = wid >> 1;
    const int rbase  = wy * 32;
    const int cbase  = wx * 16;
    const int ocbase = wx * 24;
    const float scale = 0.1020620726159658f;   // 1/sqrt(96)

    const int midx = lane >> 3, mrow = lane & 7;
    uint32_t qaddr[2], paddr[2], kaddr[2];
    #pragma unroll
    for (int mf = 0; mf < 2; mf++) {
        int row = rbase + mf * 16 + (midx & 1) * 8 + mrow;
        int col = (midx >> 1) * 4;
        qaddr[mf] = s2u(&Qs[row * QPITCH + col]);
        paddr[mf] = s2u(&Ps[row * PPITCH + col]);
    }
    #pragma unroll
    for (int f = 0; f < 2; f++)
        kaddr[f] = s2u(&Ks[(cbase + f * 8 + mrow) * KPITCH + (midx & 1) * 4]);

    for (int i = tid; i < QT * (DDIM / 4); i += 256) {
        int r = i / (DDIM / 4), c4 = (i - r * (DDIM / 4)) * 4;
        *(float4*)&Qs[r * QPITCH + c4] = *(const float4*)(Qg + r * DDIM + c4);
    }

    float oacc[2][3][4];
    #pragma unroll
    for (int mf = 0; mf < 2; mf++)
        #pragma unroll
        for (int f = 0; f < 3; f++)
            #pragma unroll
            for (int c = 0; c < 4; c++) oacc[mf][f][c] = 0.0f;

    float lsum[4] = {0.f, 0.f, 0.f, 0.f};

    for (int t = 0; t < NTILES; t++) {
        __syncthreads();

        {
            const float* Kt = Kg + (size_t)t * KT * DDIM;
            const float* Vt = Vg + (size_t)t * KT * DDIM;
            for (int i = tid; i < KT * (DDIM / 4); i += 256) {
                int r = i / (DDIM / 4), c4 = (i - r * (DDIM / 4)) * 4;
                cp_async16(s2u(Ks + r * KPITCH + c4), Kt + (size_t)r * DDIM + c4);
                cp_async16(s2u(Vs + r * VPITCH + c4), Vt + (size_t)r * DDIM + c4);
            }
            CP_COMMIT();
            asm volatile("cp.async.wait_group 0;");
        }
        __syncthreads();

        float qacc[2][2][4];
        #pragma unroll
        for (int mf = 0; mf < 2; mf++)
            #pragma unroll
            for (int f = 0; f < 2; f++)
                #pragma unroll
                for (int c = 0; c < 4; c++) qacc[mf][f][c] = 0.0f;

        #pragma unroll 4
        for (int k0 = 0; k0 < DDIM; k0 += 8) {
            uint32_t a[2][4];
            ldsm_x4(a[0][0], a[0][1], a[0][2], a[0][3], qaddr[0] + k0 * 4);
            ldsm_x4(a[1][0], a[1][1], a[1][2], a[1][3], qaddr[1] + k0 * 4);
            #pragma unroll
            for (int f = 0; f < 2; f++) {
                uint32_t b0, b1;
                ldsm_x2(b0, b1, kaddr[f] + k0 * 4);
                mma_tf32(qacc[0][f], a[0], b0, b1);
                mma_tf32(qacc[1][f], a[1], b0, b1);
            }
        }

        #pragma unroll
        for (int mf = 0; mf < 2; mf++) {
            #pragma unroll
            for (int f = 0; f < 2; f++) {
                int col = cbase + f * 8 + tig * 2;
                float p00 = __expf(qacc[mf][f][0] * scale);
                float p01 = __expf(qacc[mf][f][1] * scale);
                float p10 = __expf(qacc[mf][f][2] * scale);
                float p11 = __expf(qacc[mf][f][3] * scale);
                lsum[mf*2]   += p00 + p01;
                lsum[mf*2+1] += p10 + p11;
                *(float2*)&Ps[(rbase + mf*16 + gid) * PPITCH + col] =
                    make_float2(tf32r(p00), tf32r(p01));
                *(float2*)&Ps[(rbase + mf*16 + gid + 8) * PPITCH + col] =
                    make_float2(tf32r(p10), tf32r(p11));
            }
        }
        __syncthreads();

        #pragma unroll 4
        for (int k0 = 0; k0 < KT; k0 += 8) {
            uint32_t a[2][4];
            ldsm_x4(a[0][0], a[0][1], a[0][2], a[0][3], paddr[0] + k0 * 4);
            ldsm_x4(a[1][0], a[1][1], a[1][2], a[1][3], paddr[1] + k0 * 4);
            #pragma unroll
            for (int f = 0; f < 3; f++) {
                int n = ocbase + f * 8 + gid;
                uint32_t b0 = __float_as_uint(Vs[(k0 + tig) * VPITCH + n]);
                uint32_t b1 = __float_as_uint(Vs[(k0 + tig + 4) * VPITCH + n]);
                mma_tf32(oacc[0][f], a[0], b0, b1);
                mma_tf32(oacc[1][f], a[1], b0, b1);
            }
        }
    }

    #pragma unroll
    for (int j = 0; j < 4; j++) {
        float v = lsum[j];
        v += __shfl_xor_sync(0xffffffffu, v, 1);
        v += __shfl_xor_sync(0xffffffffu, v, 2);
        lsum[j] = v;
    }
    if (tig == 0) {
        red_s[wx * QT + rbase + gid]      = lsum[0];
        red_s[wx * QT + rbase + gid + 8]  = lsum[1];
        red_s[wx * QT + rbase + gid + 16] = lsum[2];
        red_s[wx * QT + rbase + gid + 24] = lsum[3];
    }
    __syncthreads();

    {
        int r0 = rbase + gid, r1 = r0 + 8, r2 = r0 + 16, r3 = r0 + 24;
        float l0 = red_s[r0] + red_s[QT + r0] + red_s[2*QT + r0] + red_s[3*QT + r0];
        float l1 = red_s[r1] + red_s[QT + r1] + red_s[2*QT + r1] + red_s[3*QT + r1];
        float l2 = red_s[r2] + red_s[QT + r2] + red_s[2*QT + r2] + red_s[3*QT + r2];
        float l3 = red_s[r3] + red_s[QT + r3] + red_s[2*QT + r3] + red_s[3*QT + r3];
        float i0 = 1.0f / l0, i1 = 1.0f / l1, i2 = 1.0f / l2, i3 = 1.0f / l3;
        #pragma unroll
        for (int mf = 0; mf < 2; mf++) {
            float ilo = mf ? i2 : i0, ihi = mf ? i3 : i1;
            int rlo = rbase + mf * 16 + gid, rhi = rlo + 8;
            #pragma unroll
            for (int f = 0; f < 3; f++) {
                int col = ocbase + f * 8 + tig * 2;
                float* plo = g_O + ((size_t)bh * SSL + q0 + rlo) * DDIM + col;
                float* phi = g_O + ((size_t)bh * SSL + q0 + rhi) * DDIM + col;
                plo[0] = oacc[mf][f][0] * ilo; plo[1] = oacc[mf][f][1] * ilo;
                phi[0] = oacc[mf][f][2] * ihi; phi[1] = oacc[mf][f][3] * ihi;
            }
        }
    }
}

// ---------------------------------------------------------------------------
// Kernel 3: combine heads + per-key Wo projection, tf32 MMA
// NEW: smem-staged fully-coalesced epilogue (contiguous 64d floats per s)
// ---------------------------------------------------------------------------
#define OUT_SMEM_FLOATS (64 * WPITCH + 128 * XPITCH)

__global__ __launch_bounds__(256) void k_out(
    const float* __restrict__ Wo, float* __restrict__ out)
{
    extern __shared__ float sm[];
    float* Ws = sm;                 // [64][68]  Wo native [o][k]
    float* xs = sm + 64 * WPITCH;   // [rows][68]; reused as output buffer

    const int key = blockIdx.z;
    const int b   = blockIdx.y;
    const int s0  = blockIdx.x * 64;
    const int d    = c_dim[key];
    const int rows = 64 * d;
    const int foff = c_foff[key];
    const int roff = c_roff[key];
    const int tid = threadIdx.x;

    const float* w = Wo + key * 4096;
    for (int i = tid; i < 4096; i += 256) {
        int o = i >> 6, k = i & 63;
        Ws[o * WPITCH + k] = tf32r(w[i]);
    }
    for (int i = tid; i < rows * 64; i += 256) {
        int row = i >> 6, mp = i & 63;
        int ss = row / d, dd = row - ss * d;
        xs[row * XPITCH + mp] = tf32r(
            g_O[(((size_t)(b * HH + (mp >> 3))) * SSL + s0 + ss) * DDIM
                + foff + dd * 8 + (mp & 7)]);
    }
    __syncthreads();

    const int wid  = tid >> 5;
    const int lane = tid & 31;
    const int gid  = lane >> 2;
    const int tig  = lane & 3;
    const int rbase = (wid & 3) * 16 * d;
    const int cbase = (wid >> 2) * 32;

    float qacc[2][4][4];
    #pragma unroll
    for (int mf = 0; mf < 2; mf++)
        #pragma unroll
        for (int f = 0; f < 4; f++)
            #pragma unroll
            for (int c = 0; c < 4; c++) qacc[mf][f][c] = 0.0f;

    for (int k0 = 0; k0 < 64; k0 += 8) {
        uint32_t a[2][4];
        for (int mf = 0; mf < d; mf++) {
            const float* qb = xs + (rbase + mf * 16 + gid) * XPITCH + k0;
            a[mf][0] = __float_as_uint(qb[tig]);
            a[mf][1] = __float_as_uint(qb[8 * XPITCH + tig]);
            a[mf][2] = __float_as_uint(qb[tig + 4]);
            a[mf][3] = __float_as_uint(qb[8 * XPITCH + tig + 4]);
        }
        #pragma unroll
        for (int f = 0; f < 4; f++) {
            const float* kb = Ws + (cbase + f * 8 + gid) * WPITCH + k0;
            uint32_t b0 = __float_as_uint(kb[tig]);
            uint32_t b1 = __float_as_uint(kb[tig + 4]);
            mma_tf32(qacc[0][f], a[0], b0, b1);
            if (d == 2) mma_tf32(qacc[1][f], a[1], b0, b1);
        }
    }

    // ---- staged epilogue ----
    __syncthreads();
    for (int mf = 0; mf < d; mf++) {
        int rlo = rbase + mf * 16 + gid;
        int rhi = rlo + 8;
        #pragma unroll
        for (int f = 0; f < 4; f++) {
            int col = cbase + f * 8 + tig * 2;
            xs[rlo * XPITCH + col]     = qacc[mf][f][0];
            xs[rlo * XPITCH + col + 1] = qacc[mf][f][1];
            xs[rhi * XPITCH + col]     = qacc[mf][f][2];
            xs[rhi * XPITCH + col + 1] = qacc[mf][f][3];
        }
    }
    __syncthreads();

    // per s: 64d contiguous floats at out[((b*S+s)*12 + roff)*64]
    const int q4_per_s = 16 * d;
    for (int i = tid; i < 64 * q4_per_s; i += 256) {
        int ss = i / q4_per_s, c = i - ss * q4_per_s;   // c: float4 index in chunk
        int dd = c >> 4, og4 = c & 15;
        float4 v = *(float4*)&xs[(ss * d + dd) * XPITCH + og4 * 4];
        *(float4*)(out + (((size_t)(b * SSL) + s0 + ss) * 12 + roff) * 64 + c * 4) = v;
    }
}

// ---------------------------------------------------------------------------
extern "C" void kernel_launch(void* const* d_in, const int* in_sizes, int n_in,
                              void* d_out, int out_size)
{
    const float* x0 = (const float*)d_in[0];
    const float* x1 = (const float*)d_in[1];
    const float* x2 = (const float*)d_in[2];
    const float* x3 = (const float*)d_in[3];
    const float* x4 = (const float*)d_in[4];
    const float* x5 = (const float*)d_in[5];
    const float* x6 = (const float*)d_in[6];
    const float* Wq = (const float*)d_in[7];
    const float* Wk = (const float*)d_in[8];
    const float* Wv = (const float*)d_in[9];
    const float* Wo = (const float*)d_in[10];
    float* out = (float*)d_out;

    const int proj_smem = PROJ_SMEM_FLOATS * 4;            // ~52 KB
    const int attn_smem = ATTN_SMEM_FLOATS * 4;            // ~96 KB -> 2 blocks/SM
    const int out_smem  = OUT_SMEM_FLOATS * 4;             // ~52 KB

    cudaFuncSetAttribute(k_proj, cudaFuncAttributeMaxDynamicSharedMemorySize, proj_smem);
    cudaFuncSetAttribute(k_attn, cudaFuncAttributeMaxDynamicSharedMemorySize, attn_smem);
    cudaFuncSetAttribute(k_out,  cudaFuncAttributeMaxDynamicSharedMemorySize, out_smem);

    k_proj<<<dim3(SSL / 64, BB, NKEY * 3), 256, proj_smem>>>(
        x0, x1, x2, x3, x4, x5, x6, Wq, Wk, Wv);
    k_attn<<<dim3(SSL / QT, BB * HH), 256, attn_smem>>>();
    k_out<<<dim3(SSL / 64, BB, NKEY), 256, out_smem>>>(Wo, out);
}

// round 14
// speedup vs baseline: 1.0016x; 1.0016x over previous
#include <cuda_runtime.h>
#include <cstdint>

#define BB 8
#define SSL 1024
#define HH 8
#define DDIM 96
#define NKEY 7

__constant__ int c_dim[7]  = {1, 1, 2, 2, 2, 2, 2};
__constant__ int c_foff[7] = {0, 8, 16, 32, 48, 64, 80};
__constant__ int c_roff[7] = {0, 1, 2, 4, 6, 8, 10};

__device__ float g_Q[BB * HH * SSL * DDIM];
__device__ float g_K[BB * HH * SSL * DDIM];
__device__ float g_V[BB * HH * SSL * DDIM];
__device__ float g_O[BB * HH * SSL * DDIM];

__device__ __forceinline__ float tf32r(float x) {
    uint32_t u;
    asm("cvt.rna.tf32.f32 %0, %1;" : "=r"(u) : "f"(x));
    return __uint_as_float(u);
}

__device__ __forceinline__ void mma_tf32(float* c, const uint32_t* a,
                                         uint32_t b0, uint32_t b1) {
    asm volatile(
        "mma.sync.aligned.m16n8k8.row.col.f32.tf32.tf32.f32 "
        "{%0,%1,%2,%3}, {%4,%5,%6,%7}, {%8,%9}, {%0,%1,%2,%3};"
        : "+f"(c[0]), "+f"(c[1]), "+f"(c[2]), "+f"(c[3])
        : "r"(a[0]), "r"(a[1]), "r"(a[2]), "r"(a[3]), "r"(b0), "r"(b1));
}

__device__ __forceinline__ void ldsm_x4(uint32_t& r0, uint32_t& r1,
                                        uint32_t& r2, uint32_t& r3, uint32_t addr) {
    asm volatile("ldmatrix.sync.aligned.m8n8.x4.shared.b16 {%0,%1,%2,%3}, [%4];"
        : "=r"(r0), "=r"(r1), "=r"(r2), "=r"(r3) : "r"(addr));
}
__device__ __forceinline__ void ldsm_x2(uint32_t& r0, uint32_t& r1, uint32_t addr) {
    asm volatile("ldmatrix.sync.aligned.m8n8.x2.shared.b16 {%0,%1}, [%2];"
        : "=r"(r0), "=r"(r1) : "r"(addr));
}

__device__ __forceinline__ uint32_t s2u(const void* p) {
    return (uint32_t)__cvta_generic_to_shared(p);
}
__device__ __forceinline__ void cp_async16(uint32_t saddr, const void* g) {
    asm volatile("cp.async.cg.shared.global [%0], [%1], 16;" :: "r"(saddr), "l"(g));
}
#define CP_COMMIT() asm volatile("cp.async.commit_group;")

// ---------------------------------------------------------------------------
// Kernel 1: FUSED QKV projection + head split, tf32 MMA
// grid (S/64, B, 7): one block loads x once, runs all 3 GEMMs.
// smem: 3x W [64][68] + x [rows<=128][68] = ~87 KB -> 2 blocks/SM
// ---------------------------------------------------------------------------
#define WPITCH 68
#define XPITCH 68
#define PROJ_SMEM_FLOATS (3 * 64 * WPITCH + 128 * XPITCH)

__global__ __launch_bounds__(256) void k_proj(
    const float* __restrict__ x0, const float* __restrict__ x1,
    const float* __restrict__ x2, const float* __restrict__ x3,
    const float* __restrict__ x4, const float* __restrict__ x5,
    const float* __restrict__ x6,
    const float* __restrict__ Wq, const float* __restrict__ Wk,
    const float* __restrict__ Wv)
{
    extern __shared__ float sm[];
    float* Ws = sm;                     // 3 x [64][68]
    float* xs = sm + 3 * 64 * WPITCH;   // [rows][68]

    const int key = blockIdx.z;
    const int b   = blockIdx.y;
    const int s0  = blockIdx.x * 64;
    const int d    = c_dim[key];
    const int rows = 64 * d;
    const int foff = c_foff[key];
    const int tid = threadIdx.x;

    const float* xg;
    switch (key) {
        case 0: xg = x0; break; case 1: xg = x1; break;
        case 2: xg = x2; break; case 3: xg = x3; break;
        case 4: xg = x4; break; case 5: xg = x5; break;
        default: xg = x6; break;
    }
    xg += (size_t)(b * SSL + s0) * d * 64;

    // stage all three weight matrices + the x tile (once)
    {
        const float* w0 = Wq + key * 4096;
        const float* w1 = Wk + key * 4096;
        const float* w2 = Wv + key * 4096;
        for (int i = tid; i < 4096; i += 256) {
            int o = i >> 6, k = i & 63;
            Ws[0 * 64 * WPITCH + o * WPITCH + k] = tf32r(w0[i]);
            Ws[1 * 64 * WPITCH + o * WPITCH + k] = tf32r(w1[i]);
            Ws[2 * 64 * WPITCH + o * WPITCH + k] = tf32r(w2[i]);
        }
        for (int i = tid; i < rows * 64; i += 256) {
            int r = i >> 6, c = i & 63;
            xs[r * XPITCH + c] = tf32r(xg[i]);
        }
    }
    __syncthreads();

    const int wid  = tid >> 5;
    const int lane = tid & 31;
    const int gid  = lane >> 2;
    const int tig  = lane & 3;
    const int rbase = (wid & 3) * 16 * d;
    const int cbase = (wid >> 2) * 32;

    for (int m3 = 0; m3 < 3; m3++) {
        const float* Wm = Ws + m3 * 64 * WPITCH;

        float qacc[2][4][4];
        #pragma unroll
        for (int mf = 0; mf < 2; mf++)
            #pragma unroll
            for (int f = 0; f < 4; f++)
                #pragma unroll
                for (int c = 0; c < 4; c++) qacc[mf][f][c] = 0.0f;

        for (int k0 = 0; k0 < 64; k0 += 8) {
            uint32_t a[2][4];
            for (int mf = 0; mf < d; mf++) {
                const float* qb = xs + (rbase + mf * 16 + gid) * XPITCH + k0;
                a[mf][0] = __float_as_uint(qb[tig]);
                a[mf][1] = __float_as_uint(qb[8 * XPITCH + tig]);
                a[mf][2] = __float_as_uint(qb[tig + 4]);
                a[mf][3] = __float_as_uint(qb[8 * XPITCH + tig + 4]);
            }
            #pragma unroll
            for (int f = 0; f < 4; f++) {
                const float* kb = Wm + (cbase + f * 8 + gid) * WPITCH + k0;
                uint32_t b0 = __float_as_uint(kb[tig]);
                uint32_t b1 = __float_as_uint(kb[tig + 4]);
                mma_tf32(qacc[0][f], a[0], b0, b1);
                if (d == 2) mma_tf32(qacc[1][f], a[1], b0, b1);
            }
        }

        float* dst = (m3 == 0) ? g_Q : (m3 == 1) ? g_K : g_V;
        for (int mf = 0; mf < d; mf++) {
            int rlo = rbase + mf * 16 + gid;
            int rhi = rlo + 8;
            int sslo = rlo / d, ddlo = rlo - sslo * d;
            int sshi = rhi / d, ddhi = rhi - sshi * d;
            #pragma unroll
            for (int f = 0; f < 4; f++) {
                int col = cbase + f * 8;
                int h = col >> 3;
                float* plo = dst + (((size_t)(b * HH + h)) * SSL + s0 + sslo) * DDIM
                                 + foff + ddlo * 8 + tig * 2;
                float* phi = dst + (((size_t)(b * HH + h)) * SSL + s0 + sshi) * DDIM
                                 + foff + ddhi * 8 + tig * 2;
                plo[0] = tf32r(qacc[mf][f][0]); plo[1] = tf32r(qacc[mf][f][1]);
                phi[0] = tf32r(qacc[mf][f][2]); phi[1] = tf32r(qacc[mf][f][3]);
            }
        }
    }
}

// ---------------------------------------------------------------------------
// Kernel 2: flash attention (exact R12): tf32 mma, fixed-max softmax,
// ldmatrix Q/K/P feeds, cp.async KV, 2 blocks/SM.
// ---------------------------------------------------------------------------
#define QT 64
#define KT 64
#define NTILES (SSL / KT)
#define QPITCH 100
#define KPITCH 100
#define VPITCH 104
#define PPITCH 68

#define ATTN_SMEM_FLOATS (QT*QPITCH + KT*KPITCH + KT*VPITCH + QT*PPITCH + 4*QT)

__global__ __launch_bounds__(256, 2) void k_attn()
{
    extern __shared__ float sm[];
    float* Qs    = sm;                      // [64][100]
    float* Ks    = Qs + QT * QPITCH;        // [64][100]
    float* Vs    = Ks + KT * KPITCH;        // [64][104]
    float* Ps    = Vs + KT * VPITCH;        // [64][68]
    float* red_s = Ps + QT * PPITCH;        // [4][64]

    const int bh = blockIdx.y;
    const int q0 = blockIdx.x * QT;
    const float* Qg = g_Q + ((size_t)bh * SSL + q0) * DDIM;
    const float* Kg = g_K + (size_t)bh * SSL * DDIM;
    const float* Vg = g_V + (size_t)bh * SSL * DDIM;

    const int tid  = threadIdx.x;
    const int wid  = tid >> 5;
    const int lane = tid & 31;
    const int gid  = lane >> 2;
    const int tig  = lane & 3;
    const int wy   = wid & 1;
    const int wx   = wid >> 1;
    const int rbase  = wy * 32;
    const int cbase  = wx * 16;
    const int ocbase = wx * 24;
    const float scale = 0.1020620726159658f;   // 1/sqrt(96)

    const int midx = lane >> 3, mrow = lane & 7;
    uint32_t qaddr[2], paddr[2], kaddr[2];
    #pragma unroll
    for (int mf = 0; mf < 2; mf++) {
        int row = rbase + mf * 16 + (midx & 1) * 8 + mrow;
        int col = (midx >> 1) * 4;
        qaddr[mf] = s2u(&Qs[row * QPITCH + col]);
        paddr[mf] = s2u(&Ps[row * PPITCH + col]);
    }
    #pragma unroll
    for (int f = 0; f < 2; f++)
        kaddr[f] = s2u(&Ks[(cbase + f * 8 + mrow) * KPITCH + (midx & 1) * 4]);

    for (int i = tid; i < QT * (DDIM / 4); i += 256) {
        int r = i / (DDIM / 4), c4 = (i - r * (DDIM / 4)) * 4;
        *(float4*)&Qs[r * QPITCH + c4] = *(const float4*)(Qg + r * DDIM + c4);
    }

    float oacc[2][3][4];
    #pragma unroll
    for (int mf = 0; mf < 2; mf++)
        #pragma unroll
        for (int f = 0; f < 3; f++)
            #pragma unroll
            for (int c = 0; c < 4; c++) oacc[mf][f][c] = 0.0f;

    float lsum[4] = {0.f, 0.f, 0.f, 0.f};

    for (int t = 0; t < NTILES; t++) {
        __syncthreads();

        {
            const float* Kt = Kg + (size_t)t * KT * DDIM;
            const float* Vt = Vg + (size_t)t * KT * DDIM;
            for (int i = tid; i < KT * (DDIM / 4); i += 256) {
                int r = i / (DDIM / 4), c4 = (i - r * (DDIM / 4)) * 4;
                cp_async16(s2u(Ks + r * KPITCH + c4), Kt + (size_t)r * DDIM + c4);
                cp_async16(s2u(Vs + r * VPITCH + c4), Vt + (size_t)r * DDIM + c4);
            }
            CP_COMMIT();
            asm volatile("cp.async.wait_group 0;");
        }
        __syncthreads();

        float qacc[2][2][4];
        #pragma unroll
        for (int mf = 0; mf < 2; mf++)
            #pragma unroll
            for (int f = 0; f < 2; f++)
                #pragma unroll
                for (int c = 0; c < 4; c++) qacc[mf][f][c] = 0.0f;

        #pragma unroll 4
        for (int k0 = 0; k0 < DDIM; k0 += 8) {
            uint32_t a[2][4];
            ldsm_x4(a[0][0], a[0][1], a[0][2], a[0][3], qaddr[0] + k0 * 4);
            ldsm_x4(a[1][0], a[1][1], a[1][2], a[1][3], qaddr[1] + k0 * 4);
            #pragma unroll
            for (int f = 0; f < 2; f++) {
                uint32_t b0, b1;
                ldsm_x2(b0, b1, kaddr[f] + k0 * 4);
                mma_tf32(qacc[0][f], a[0], b0, b1);
                mma_tf32(qacc[1][f], a[1], b0, b1);
            }
        }

        #pragma unroll
        for (int mf = 0; mf < 2; mf++) {
            #pragma unroll
            for (int f = 0; f < 2; f++) {
                int col = cbase + f * 8 + tig * 2;
                float p00 = __expf(qacc[mf][f][0] * scale);
                float p01 = __expf(qacc[mf][f][1] * scale);
                float p10 = __expf(qacc[mf][f][2] * scale);
                float p11 = __expf(qacc[mf][f][3] * scale);
                lsum[mf*2]   += p00 + p01;
                lsum[mf*2+1] += p10 + p11;
                *(float2*)&Ps[(rbase + mf*16 + gid) * PPITCH + col] =
                    make_float2(tf32r(p00), tf32r(p01));
                *(float2*)&Ps[(rbase + mf*16 + gid + 8) * PPITCH + col] =
                    make_float2(tf32r(p10), tf32r(p11));
            }
        }
        __syncthreads();

        #pragma unroll 4
        for (int k0 = 0; k0 < KT; k0 += 8) {
            uint32_t a[2][4];
            ldsm_x4(a[0][0], a[0][1], a[0][2], a[0][3], paddr[0] + k0 * 4);
            ldsm_x4(a[1][0], a[1][1], a[1][2], a[1][3], paddr[1] + k0 * 4);
            #pragma unroll
            for (int f = 0; f < 3; f++) {
                int n = ocbase + f * 8 + gid;
                uint32_t b0 = __float_as_uint(Vs[(k0 + tig) * VPITCH + n]);
                uint32_t b1 = __float_as_uint(Vs[(k0 + tig + 4) * VPITCH + n]);
                mma_tf32(oacc[0][f], a[0], b0, b1);
                mma_tf32(oacc[1][f], a[1], b0, b1);
            }
        }
    }

    #pragma unroll
    for (int j = 0; j < 4; j++) {
        float v = lsum[j];
        v += __shfl_xor_sync(0xffffffffu, v, 1);
        v += __shfl_xor_sync(0xffffffffu, v, 2);
        lsum[j] = v;
    }
    if (tig == 0) {
        red_s[wx * QT + rbase + gid]      = lsum[0];
        red_s[wx * QT + rbase + gid + 8]  = lsum[1];
        red_s[wx * QT + rbase + gid + 16] = lsum[2];
        red_s[wx * QT + rbase + gid + 24] = lsum[3];
    }
    __syncthreads();

    {
        int r0 = rbase + gid, r1 = r0 + 8, r2 = r0 + 16, r3 = r0 + 24;
        float l0 = red_s[r0] + red_s[QT + r0] + red_s[2*QT + r0] + red_s[3*QT + r0];
        float l1 = red_s[r1] + red_s[QT + r1] + red_s[2*QT + r1] + red_s[3*QT + r1];
        float l2 = red_s[r2] + red_s[QT + r2] + red_s[2*QT + r2] + red_s[3*QT + r2];
        float l3 = red_s[r3] + red_s[QT + r3] + red_s[2*QT + r3] + red_s[3*QT + r3];
        float i0 = 1.0f / l0, i1 = 1.0f / l1, i2 = 1.0f / l2, i3 = 1.0f / l3;
        #pragma unroll
        for (int mf = 0; mf < 2; mf++) {
            float ilo = mf ? i2 : i0, ihi = mf ? i3 : i1;
            int rlo = rbase + mf * 16 + gid, rhi = rlo + 8;
            #pragma unroll
            for (int f = 0; f < 3; f++) {
                int col = ocbase + f * 8 + tig * 2;
                float* plo = g_O + ((size_t)bh * SSL + q0 + rlo) * DDIM + col;
                float* phi = g_O + ((size_t)bh * SSL + q0 + rhi) * DDIM + col;
                plo[0] = oacc[mf][f][0] * ilo; plo[1] = oacc[mf][f][1] * ilo;
                phi[0] = oacc[mf][f][2] * ihi; phi[1] = oacc[mf][f][3] * ihi;
            }
        }
    }
}

// ---------------------------------------------------------------------------
// Kernel 3: combine heads + per-key Wo projection, tf32 MMA (exact R12)
// ---------------------------------------------------------------------------
#define OUT_SMEM_FLOATS (64 * WPITCH + 128 * XPITCH)

__global__ __launch_bounds__(256) void k_out(
    const float* __restrict__ Wo, float* __restrict__ out)
{
    extern __shared__ float sm[];
    float* Ws = sm;                 // [64][68]  Wo native [o][k]
    float* xs = sm + 64 * WPITCH;   // [rows][68] combined heads

    const int key = blockIdx.z;
    const int b   = blockIdx.y;
    const int s0  = blockIdx.x * 64;
    const int d    = c_dim[key];
    const int rows = 64 * d;
    const int foff = c_foff[key];
    const int roff = c_roff[key];
    const int tid = threadIdx.x;

    const float* w = Wo + key * 4096;
    for (int i = tid; i < 4096; i += 256) {
        int o = i >> 6, k = i & 63;
        Ws[o * WPITCH + k] = tf32r(w[i]);
    }
    for (int i = tid; i < rows * 64; i += 256) {
        int row = i >> 6, mp = i & 63;
        int ss = row / d, dd = row - ss * d;
        xs[row * XPITCH + mp] = tf32r(
            g_O[(((size_t)(b * HH + (mp >> 3))) * SSL + s0 + ss) * DDIM
                + foff + dd * 8 + (mp & 7)]);
    }
    __syncthreads();

    const int wid  = tid >> 5;
    const int lane = tid & 31;
    const int gid  = lane >> 2;
    const int tig  = lane & 3;
    const int rbase = (wid & 3) * 16 * d;
    const int cbase = (wid >> 2) * 32;

    float qacc[2][4][4];
    #pragma unroll
    for (int mf = 0; mf < 2; mf++)
        #pragma unroll
        for (int f = 0; f < 4; f++)
            #pragma unroll
            for (int c = 0; c < 4; c++) qacc[mf][f][c] = 0.0f;

    for (int k0 = 0; k0 < 64; k0 += 8) {
        uint32_t a[2][4];
        for (int mf = 0; mf < d; mf++) {
            const float* qb = xs + (rbase + mf * 16 + gid) * XPITCH + k0;
            a[mf][0] = __float_as_uint(qb[tig]);
            a[mf][1] = __float_as_uint(qb[8 * XPITCH + tig]);
            a[mf][2] = __float_as_uint(qb[tig + 4]);
            a[mf][3] = __float_as_uint(qb[8 * XPITCH + tig + 4]);
        }
        #pragma unroll
        for (int f = 0; f < 4; f++) {
            const float* kb = Ws + (cbase + f * 8 + gid) * WPITCH + k0;
            uint32_t b0 = __float_as_uint(kb[tig]);
            uint32_t b1 = __float_as_uint(kb[tig + 4]);
            mma_tf32(qacc[0][f], a[0], b0, b1);
            if (d == 2) mma_tf32(qacc[1][f], a[1], b0, b1);
        }
    }

    for (int mf = 0; mf < d; mf++) {
        int rlo = rbase + mf * 16 + gid;
        int rhi = rlo + 8;
        int sslo = rlo / d, ddlo = rlo - sslo * d;
        int sshi = rhi / d, ddhi = rhi - sshi * d;
        #pragma unroll
        for (int f = 0; f < 4; f++) {
            int col = cbase + f * 8 + tig * 2;
            float* plo = out + (((size_t)(b * SSL) + s0 + sslo) * 12 + roff + ddlo) * 64 + col;
            float* phi = out + (((size_t)(b * SSL) + s0 + sshi) * 12 + roff + ddhi) * 64 + col;
            plo[0] = qacc[mf][f][0]; plo[1] = qacc[mf][f][1];
            phi[0] = qacc[mf][f][2]; phi[1] = qacc[mf][f][3];
        }
    }
}

// ---------------------------------------------------------------------------
extern "C" void kernel_launch(void* const* d_in, const int* in_sizes, int n_in,
                              void* d_out, int out_size)
{
    const float* x0 = (const float*)d_in[0];
    const float* x1 = (const float*)d_in[1];
    const float* x2 = (const float*)d_in[2];
    const float* x3 = (const float*)d_in[3];
    const float* x4 = (const float*)d_in[4];
    const float* x5 = (const float*)d_in[5];
    const float* x6 = (const float*)d_in[6];
    const float* Wq = (const float*)d_in[7];
    const float* Wk = (const float*)d_in[8];
    const float* Wv = (const float*)d_in[9];
    const float* Wo = (const float*)d_in[10];
    float* out = (float*)d_out;

    const int proj_smem = PROJ_SMEM_FLOATS * 4;            // ~87 KB -> 2 blocks/SM
    const int attn_smem = ATTN_SMEM_FLOATS * 4;            // ~96 KB -> 2 blocks/SM
    const int out_smem  = OUT_SMEM_FLOATS * 4;             // ~52 KB

    cudaFuncSetAttribute(k_proj, cudaFuncAttributeMaxDynamicSharedMemorySize, proj_smem);
    cudaFuncSetAttribute(k_attn, cudaFuncAttributeMaxDynamicSharedMemorySize, attn_smem);
    cudaFuncSetAttribute(k_out,  cudaFuncAttributeMaxDynamicSharedMemorySize, out_smem);

    k_proj<<<dim3(SSL / 64, BB, NKEY), 256, proj_smem>>>(
        x0, x1, x2, x3, x4, x5, x6, Wq, Wk, Wv);
    k_attn<<<dim3(SSL / QT, BB * HH), 256, attn_smem>>>();
    k_out<<<dim3(SSL / 64, BB, NKEY), 256, out_smem>>>(Wo, out);
}

// round 15
// speedup vs baseline: 1.0575x; 1.0558x over previous
#include <cuda_runtime.h>
#include <cstdint>

#define BB 8
#define SSL 1024
#define HH 8
#define DDIM 96
#define NKEY 7

__constant__ int c_dim[7]  = {1, 1, 2, 2, 2, 2, 2};
__constant__ int c_foff[7] = {0, 8, 16, 32, 48, 64, 80};
__constant__ int c_roff[7] = {0, 1, 2, 4, 6, 8, 10};

__device__ float g_Q[BB * HH * SSL * DDIM];
__device__ float g_K[BB * HH * SSL * DDIM];
__device__ float g_V[BB * HH * SSL * DDIM];
__device__ float g_O[BB * HH * SSL * DDIM];

__device__ __forceinline__ float tf32r(float x) {
    uint32_t u;
    asm("cvt.rna.tf32.f32 %0, %1;" : "=r"(u) : "f"(x));
    return __uint_as_float(u);
}

__device__ __forceinline__ void mma_tf32(float* c, const uint32_t* a,
                                         uint32_t b0, uint32_t b1) {
    asm volatile(
        "mma.sync.aligned.m16n8k8.row.col.f32.tf32.tf32.f32 "
        "{%0,%1,%2,%3}, {%4,%5,%6,%7}, {%8,%9}, {%0,%1,%2,%3};"
        : "+f"(c[0]), "+f"(c[1]), "+f"(c[2]), "+f"(c[3])
        : "r"(a[0]), "r"(a[1]), "r"(a[2]), "r"(a[3]), "r"(b0), "r"(b1));
}

__device__ __forceinline__ void ldsm_x4(uint32_t& r0, uint32_t& r1,
                                        uint32_t& r2, uint32_t& r3, uint32_t addr) {
    asm volatile("ldmatrix.sync.aligned.m8n8.x4.shared.b16 {%0,%1,%2,%3}, [%4];"
        : "=r"(r0), "=r"(r1), "=r"(r2), "=r"(r3) : "r"(addr));
}
__device__ __forceinline__ void ldsm_x2(uint32_t& r0, uint32_t& r1, uint32_t addr) {
    asm volatile("ldmatrix.sync.aligned.m8n8.x2.shared.b16 {%0,%1}, [%2];"
        : "=r"(r0), "=r"(r1) : "r"(addr));
}

__device__ __forceinline__ uint32_t s2u(const void* p) {
    return (uint32_t)__cvta_generic_to_shared(p);
}
__device__ __forceinline__ void cp_async16(uint32_t saddr, const void* g) {
    asm volatile("cp.async.cg.shared.global [%0], [%1], 16;" :: "r"(saddr), "l"(g));
}
#define CP_COMMIT() asm volatile("cp.async.commit_group;")

// ---------------------------------------------------------------------------
// Kernel 1: FUSED QKV projection + head split, tf32 MMA, float4 staging
// grid (S/64, B, 7); smem ~87 KB -> 2 blocks/SM
// ---------------------------------------------------------------------------
#define WPITCH 68
#define XPITCH 68
#define PROJ_SMEM_FLOATS (3 * 64 * WPITCH + 128 * XPITCH)

__global__ __launch_bounds__(256) void k_proj(
    const float* __restrict__ x0, const float* __restrict__ x1,
    const float* __restrict__ x2, const float* __restrict__ x3,
    const float* __restrict__ x4, const float* __restrict__ x5,
    const float* __restrict__ x6,
    const float* __restrict__ Wq, const float* __restrict__ Wk,
    const float* __restrict__ Wv)
{
    extern __shared__ float sm[];
    float* Ws = sm;                     // 3 x [64][68]
    float* xs = sm + 3 * 64 * WPITCH;   // [rows][68]

    const int key = blockIdx.z;
    const int b   = blockIdx.y;
    const int s0  = blockIdx.x * 64;
    const int d    = c_dim[key];
    const int rows = 64 * d;
    const int foff = c_foff[key];
    const int tid = threadIdx.x;

    const float* xg;
    switch (key) {
        case 0: xg = x0; break; case 1: xg = x1; break;
        case 2: xg = x2; break; case 3: xg = x3; break;
        case 4: xg = x4; break; case 5: xg = x5; break;
        default: xg = x6; break;
    }
    xg += (size_t)(b * SSL + s0) * d * 64;

    // float4 staging: 3 W matrices + x tile (x loaded once)
    {
        const float4* w0 = (const float4*)(Wq + key * 4096);
        const float4* w1 = (const float4*)(Wk + key * 4096);
        const float4* w2 = (const float4*)(Wv + key * 4096);
        for (int i = tid; i < 1024; i += 256) {       // 1024 float4 = 4096 floats
            int o = i >> 4, k4 = (i & 15) * 4;
            float4 a = w0[i], bq = w1[i], c = w2[i];
            float* p0 = Ws + 0 * 64 * WPITCH + o * WPITCH + k4;
            float* p1 = Ws + 1 * 64 * WPITCH + o * WPITCH + k4;
            float* p2 = Ws + 2 * 64 * WPITCH + o * WPITCH + k4;
            p0[0]=tf32r(a.x);  p0[1]=tf32r(a.y);  p0[2]=tf32r(a.z);  p0[3]=tf32r(a.w);
            p1[0]=tf32r(bq.x); p1[1]=tf32r(bq.y); p1[2]=tf32r(bq.z); p1[3]=tf32r(bq.w);
            p2[0]=tf32r(c.x);  p2[1]=tf32r(c.y);  p2[2]=tf32r(c.z);  p2[3]=tf32r(c.w);
        }
        const float4* xg4 = (const float4*)xg;
        for (int i = tid; i < rows * 16; i += 256) {  // rows*16 float4
            int r = i >> 4, k4 = (i & 15) * 4;
            float4 v = xg4[i];
            float* p = xs + r * XPITCH + k4;
            p[0]=tf32r(v.x); p[1]=tf32r(v.y); p[2]=tf32r(v.z); p[3]=tf32r(v.w);
        }
    }
    __syncthreads();

    const int wid  = tid >> 5;
    const int lane = tid & 31;
    const int gid  = lane >> 2;
    const int tig  = lane & 3;
    const int rbase = (wid & 3) * 16 * d;
    const int cbase = (wid >> 2) * 32;

    for (int m3 = 0; m3 < 3; m3++) {
        const float* Wm = Ws + m3 * 64 * WPITCH;

        float qacc[2][4][4];
        #pragma unroll
        for (int mf = 0; mf < 2; mf++)
            #pragma unroll
            for (int f = 0; f < 4; f++)
                #pragma unroll
                for (int c = 0; c < 4; c++) qacc[mf][f][c] = 0.0f;

        for (int k0 = 0; k0 < 64; k0 += 8) {
            uint32_t a[2][4];
            for (int mf = 0; mf < d; mf++) {
                const float* qb = xs + (rbase + mf * 16 + gid) * XPITCH + k0;
                a[mf][0] = __float_as_uint(qb[tig]);
                a[mf][1] = __float_as_uint(qb[8 * XPITCH + tig]);
                a[mf][2] = __float_as_uint(qb[tig + 4]);
                a[mf][3] = __float_as_uint(qb[8 * XPITCH + tig + 4]);
            }
            #pragma unroll
            for (int f = 0; f < 4; f++) {
                const float* kb = Wm + (cbase + f * 8 + gid) * WPITCH + k0;
                uint32_t b0 = __float_as_uint(kb[tig]);
                uint32_t b1 = __float_as_uint(kb[tig + 4]);
                mma_tf32(qacc[0][f], a[0], b0, b1);
                if (d == 2) mma_tf32(qacc[1][f], a[1], b0, b1);
            }
        }

        float* dst = (m3 == 0) ? g_Q : (m3 == 1) ? g_K : g_V;
        for (int mf = 0; mf < d; mf++) {
            int rlo = rbase + mf * 16 + gid;
            int rhi = rlo + 8;
            int sslo = rlo / d, ddlo = rlo - sslo * d;
            int sshi = rhi / d, ddhi = rhi - sshi * d;
            #pragma unroll
            for (int f = 0; f < 4; f++) {
                int col = cbase + f * 8;
                int h = col >> 3;
                float* plo = dst + (((size_t)(b * HH + h)) * SSL + s0 + sslo) * DDIM
                                 + foff + ddlo * 8 + tig * 2;
                float* phi = dst + (((size_t)(b * HH + h)) * SSL + s0 + sshi) * DDIM
                                 + foff + ddhi * 8 + tig * 2;
                plo[0] = tf32r(qacc[mf][f][0]); plo[1] = tf32r(qacc[mf][f][1]);
                phi[0] = tf32r(qacc[mf][f][2]); phi[1] = tf32r(qacc[mf][f][3]);
            }
        }
    }
}

// ---------------------------------------------------------------------------
// Kernel 2: flash attention, tf32 mma, fixed-max softmax, ldmatrix feeds.
// NEW: split cp.async groups — K waited before QK, V drains during QK+exp.
// ---------------------------------------------------------------------------
#define QT 64
#define KT 64
#define NTILES (SSL / KT)
#define QPITCH 100
#define KPITCH 100
#define VPITCH 104
#define PPITCH 68

#define ATTN_SMEM_FLOATS (QT*QPITCH + KT*KPITCH + KT*VPITCH + QT*PPITCH + 4*QT)

__global__ __launch_bounds__(256, 2) void k_attn()
{
    extern __shared__ float sm[];
    float* Qs    = sm;                      // [64][100]
    float* Ks    = Qs + QT * QPITCH;        // [64][100]
    float* Vs    = Ks + KT * KPITCH;        // [64][104]
    float* Ps    = Vs + KT * VPITCH;        // [64][68]
    float* red_s = Ps + QT * PPITCH;        // [4][64]

    const int bh = blockIdx.y;
    const int q0 = blockIdx.x * QT;
    const float* Qg = g_Q + ((size_t)bh * SSL + q0) * DDIM;
    const float* Kg = g_K + (size_t)bh * SSL * DDIM;
    const float* Vg = g_V + (size_t)bh * SSL * DDIM;

    const int tid  = threadIdx.x;
    const int wid  = tid >> 5;
    const int lane = tid & 31;
    const int gid  = lane >> 2;
    const int tig  = lane & 3;
    const int wy   = wid & 1;
    const int wx   = wid >> 1;
    const int rbase  = wy * 32;
    const int cbase  = wx * 16;
    const int ocbase = wx * 24;
    const float scale = 0.1020620726159658f;   // 1/sqrt(96)

    const int midx = lane >> 3, mrow = lane & 7;
    uint32_t qaddr[2], paddr[2], kaddr[2];
    #pragma unroll
    for (int mf = 0; mf < 2; mf++) {
        int row = rbase + mf * 16 + (midx & 1) * 8 + mrow;
        int col = (midx >> 1) * 4;
        qaddr[mf] = s2u(&Qs[row * QPITCH + col]);
        paddr[mf] = s2u(&Ps[row * PPITCH + col]);
    }
    #pragma unroll
    for (int f = 0; f < 2; f++)
        kaddr[f] = s2u(&Ks[(cbase + f * 8 + mrow) * KPITCH + (midx & 1) * 4]);

    for (int i = tid; i < QT * (DDIM / 4); i += 256) {
        int r = i / (DDIM / 4), c4 = (i - r * (DDIM / 4)) * 4;
        *(float4*)&Qs[r * QPITCH + c4] = *(const float4*)(Qg + r * DDIM + c4);
    }

    float oacc[2][3][4];
    #pragma unroll
    for (int mf = 0; mf < 2; mf++)
        #pragma unroll
        for (int f = 0; f < 3; f++)
            #pragma unroll
            for (int c = 0; c < 4; c++) oacc[mf][f][c] = 0.0f;

    float lsum[4] = {0.f, 0.f, 0.f, 0.f};

    for (int t = 0; t < NTILES; t++) {
        __syncthreads();   // previous tile's K/V/P fully consumed

        {
            const float* Kt = Kg + (size_t)t * KT * DDIM;
            const float* Vt = Vg + (size_t)t * KT * DDIM;
            // group A: K
            for (int i = tid; i < KT * (DDIM / 4); i += 256) {
                int r = i / (DDIM / 4), c4 = (i - r * (DDIM / 4)) * 4;
                cp_async16(s2u(Ks + r * KPITCH + c4), Kt + (size_t)r * DDIM + c4);
            }
            CP_COMMIT();
            // group B: V
            for (int i = tid; i < KT * (DDIM / 4); i += 256) {
                int r = i / (DDIM / 4), c4 = (i - r * (DDIM / 4)) * 4;
                cp_async16(s2u(Vs + r * VPITCH + c4), Vt + (size_t)r * DDIM + c4);
            }
            CP_COMMIT();
            asm volatile("cp.async.wait_group 1;");   // K done; V in flight
        }
        __syncthreads();   // K visible block-wide

        // ---- S = Q K^T (warp 32x16), ldmatrix feeds; V drains meanwhile ----
        float qacc[2][2][4];
        #pragma unroll
        for (int mf = 0; mf < 2; mf++)
            #pragma unroll
            for (int f = 0; f < 2; f++)
                #pragma unroll
                for (int c = 0; c < 4; c++) qacc[mf][f][c] = 0.0f;

        #pragma unroll 4
        for (int k0 = 0; k0 < DDIM; k0 += 8) {
            uint32_t a[2][4];
            ldsm_x4(a[0][0], a[0][1], a[0][2], a[0][3], qaddr[0] + k0 * 4);
            ldsm_x4(a[1][0], a[1][1], a[1][2], a[1][3], qaddr[1] + k0 * 4);
            #pragma unroll
            for (int f = 0; f < 2; f++) {
                uint32_t b0, b1;
                ldsm_x2(b0, b1, kaddr[f] + k0 * 4);
                mma_tf32(qacc[0][f], a[0], b0, b1);
                mma_tf32(qacc[1][f], a[1], b0, b1);
            }
        }

        // ---- P = exp(S*scale); accumulate row sums ----
        #pragma unroll
        for (int mf = 0; mf < 2; mf++) {
            #pragma unroll
            for (int f = 0; f < 2; f++) {
                int col = cbase + f * 8 + tig * 2;
                float p00 = __expf(qacc[mf][f][0] * scale);
                float p01 = __expf(qacc[mf][f][1] * scale);
                float p10 = __expf(qacc[mf][f][2] * scale);
                float p11 = __expf(qacc[mf][f][3] * scale);
                lsum[mf*2]   += p00 + p01;
                lsum[mf*2+1] += p10 + p11;
                *(float2*)&Ps[(rbase + mf*16 + gid) * PPITCH + col] =
                    make_float2(tf32r(p00), tf32r(p01));
                *(float2*)&Ps[(rbase + mf*16 + gid + 8) * PPITCH + col] =
                    make_float2(tf32r(p10), tf32r(p11));
            }
        }
        asm volatile("cp.async.wait_group 0;");   // V arrived (per-thread)
        __syncthreads();                          // P + V visible block-wide

        // ---- O += P V (warp 32x24), P via ldmatrix ----
        #pragma unroll 4
        for (int k0 = 0; k0 < KT; k0 += 8) {
            uint32_t a[2][4];
            ldsm_x4(a[0][0], a[0][1], a[0][2], a[0][3], paddr[0] + k0 * 4);
            ldsm_x4(a[1][0], a[1][1], a[1][2], a[1][3], paddr[1] + k0 * 4);
            #pragma unroll
            for (int f = 0; f < 3; f++) {
                int n = ocbase + f * 8 + gid;
                uint32_t b0 = __float_as_uint(Vs[(k0 + tig) * VPITCH + n]);
                uint32_t b1 = __float_as_uint(Vs[(k0 + tig + 4) * VPITCH + n]);
                mma_tf32(oacc[0][f], a[0], b0, b1);
                mma_tf32(oacc[1][f], a[1], b0, b1);
            }
        }
    }

    // ---- final row-sum reduction ----
    #pragma unroll
    for (int j = 0; j < 4; j++) {
        float v = lsum[j];
        v += __shfl_xor_sync(0xffffffffu, v, 1);
        v += __shfl_xor_sync(0xffffffffu, v, 2);
        lsum[j] = v;
    }
    if (tig == 0) {
        red_s[wx * QT + rbase + gid]      = lsum[0];
        red_s[wx * QT + rbase + gid + 8]  = lsum[1];
        red_s[wx * QT + rbase + gid + 16] = lsum[2];
        red_s[wx * QT + rbase + gid + 24] = lsum[3];
    }
    __syncthreads();

    {
        int r0 = rbase + gid, r1 = r0 + 8, r2 = r0 + 16, r3 = r0 + 24;
        float l0 = red_s[r0] + red_s[QT + r0] + red_s[2*QT + r0] + red_s[3*QT + r0];
        float l1 = red_s[r1] + red_s[QT + r1] + red_s[2*QT + r1] + red_s[3*QT + r1];
        float l2 = red_s[r2] + red_s[QT + r2] + red_s[2*QT + r2] + red_s[3*QT + r2];
        float l3 = red_s[r3] + red_s[QT + r3] + red_s[2*QT + r3] + red_s[3*QT + r3];
        float i0 = 1.0f / l0, i1 = 1.0f / l1, i2 = 1.0f / l2, i3 = 1.0f / l3;
        #pragma unroll
        for (int mf = 0; mf < 2; mf++) {
            float ilo = mf ? i2 : i0, ihi = mf ? i3 : i1;
            int rlo = rbase + mf * 16 + gid, rhi = rlo + 8;
            #pragma unroll
            for (int f = 0; f < 3; f++) {
                int col = ocbase + f * 8 + tig * 2;
                float* plo = g_O + ((size_t)bh * SSL + q0 + rlo) * DDIM + col;
                float* phi = g_O + ((size_t)bh * SSL + q0 + rhi) * DDIM + col;
                plo[0] = oacc[mf][f][0] * ilo; plo[1] = oacc[mf][f][1] * ilo;
                phi[0] = oacc[mf][f][2] * ihi; phi[1] = oacc[mf][f][3] * ihi;
            }
        }
    }
}

// ---------------------------------------------------------------------------
// Kernel 3: combine heads + per-key Wo projection, tf32 MMA (exact R12)
// ---------------------------------------------------------------------------
#define OUT_SMEM_FLOATS (64 * WPITCH + 128 * XPITCH)

__global__ __launch_bounds__(256) void k_out(
    const float* __restrict__ Wo, float* __restrict__ out)
{
    extern __shared__ float sm[];
    float* Ws = sm;                 // [64][68]  Wo native [o][k]
    float* xs = sm + 64 * WPITCH;   // [rows][68] combined heads

    const int key = blockIdx.z;
    const int b   = blockIdx.y;
    const int s0  = blockIdx.x * 64;
    const int d    = c_dim[key];
    const int rows = 64 * d;
    const int foff = c_foff[key];
    const int roff = c_roff[key];
    const int tid = threadIdx.x;

    const float* w = Wo + key * 4096;
    for (int i = tid; i < 4096; i += 256) {
        int o = i >> 6, k = i & 63;
        Ws[o * WPITCH + k] = tf32r(w[i]);
    }
    for (int i = tid; i < rows * 64; i += 256) {
        int row = i >> 6, mp = i & 63;
        int ss = row / d, dd = row - ss * d;
        xs[row * XPITCH + mp] = tf32r(
            g_O[(((size_t)(b * HH + (mp >> 3))) * SSL + s0 + ss) * DDIM
                + foff + dd * 8 + (mp & 7)]);
    }
    __syncthreads();

    const int wid  = tid >> 5;
    const int lane = tid & 31;
    const int gid  = lane >> 2;
    const int tig  = lane & 3;
    const int rbase = (wid & 3) * 16 * d;
    const int cbase = (wid >> 2) * 32;

    float qacc[2][4][4];
    #pragma unroll
    for (int mf = 0; mf < 2; mf++)
        #pragma unroll
        for (int f = 0; f < 4; f++)
            #pragma unroll
            for (int c = 0; c < 4; c++) qacc[mf][f][c] = 0.0f;

    for (int k0 = 0; k0 < 64; k0 += 8) {
        uint32_t a[2][4];
        for (int mf = 0; mf < d; mf++) {
            const float* qb = xs + (rbase + mf * 16 + gid) * XPITCH + k0;
            a[mf][0] = __float_as_uint(qb[tig]);
            a[mf][1] = __float_as_uint(qb[8 * XPITCH + tig]);
            a[mf][2] = __float_as_uint(qb[tig + 4]);
            a[mf][3] = __float_as_uint(qb[8 * XPITCH + tig + 4]);
        }
        #pragma unroll
        for (int f = 0; f < 4; f++) {
            const float* kb = Ws + (cbase + f * 8 + gid) * WPITCH + k0;
            uint32_t b0 = __float_as_uint(kb[tig]);
            uint32_t b1 = __float_as_uint(kb[tig + 4]);
            mma_tf32(qacc[0][f], a[0], b0, b1);
            if (d == 2) mma_tf32(qacc[1][f], a[1], b0, b1);
        }
    }

    for (int mf = 0; mf < d; mf++) {
        int rlo = rbase + mf * 16 + gid;
        int rhi = rlo + 8;
        int sslo = rlo / d, ddlo = rlo - sslo * d;
        int sshi = rhi / d, ddhi = rhi - sshi * d;
        #pragma unroll
        for (int f = 0; f < 4; f++) {
            int col = cbase + f * 8 + tig * 2;
            float* plo = out + (((size_t)(b * SSL) + s0 + sslo) * 12 + roff + ddlo) * 64 + col;
            float* phi = out + (((size_t)(b * SSL) + s0 + sshi) * 12 + roff + ddhi) * 64 + col;
            plo[0] = qacc[mf][f][0]; plo[1] = qacc[mf][f][1];
            phi[0] = qacc[mf][f][2]; phi[1] = qacc[mf][f][3];
        }
    }
}

// ---------------------------------------------------------------------------
extern "C" void kernel_launch(void* const* d_in, const int* in_sizes, int n_in,
                              void* d_out, int out_size)
{
    const float* x0 = (const float*)d_in[0];
    const float* x1 = (const float*)d_in[1];
    const float* x2 = (const float*)d_in[2];
    const float* x3 = (const float*)d_in[3];
    const float* x4 = (const float*)d_in[4];
    const float* x5 = (const float*)d_in[5];
    const float* x6 = (const float*)d_in[6];
    const float* Wq = (const float*)d_in[7];
    const float* Wk = (const float*)d_in[8];
    const float* Wv = (const float*)d_in[9];
    const float* Wo = (const float*)d_in[10];
    float* out = (float*)d_out;

    const int proj_smem = PROJ_SMEM_FLOATS * 4;            // ~87 KB -> 2 blocks/SM
    const int attn_smem = ATTN_SMEM_FLOATS * 4;            // ~96 KB -> 2 blocks/SM
    const int out_smem  = OUT_SMEM_FLOATS * 4;             // ~52 KB

    cudaFuncSetAttribute(k_proj, cudaFuncAttributeMaxDynamicSharedMemorySize, proj_smem);
    cudaFuncSetAttribute(k_attn, cudaFuncAttributeMaxDynamicSharedMemorySize, attn_smem);
    cudaFuncSetAttribute(k_out,  cudaFuncAttributeMaxDynamicSharedMemorySize, out_smem);

    k_proj<<<dim3(SSL / 64, BB, NKEY), 256, proj_smem>>>(
        x0, x1, x2, x3, x4, x5, x6, Wq, Wk, Wv);
    k_attn<<<dim3(SSL / QT, BB * HH), 256, attn_smem>>>();
    k_out<<<dim3(SSL / 64, BB, NKEY), 256, out_smem>>>(Wo, out);
}

// round 16
// speedup vs baseline: 1.1144x; 1.0538x over previous
#include <cuda_runtime.h>
#include <cstdint>

#define BB 8
#define SSL 1024
#define HH 8
#define DDIM 96
#define NKEY 7

__constant__ int c_dim[7]  = {1, 1, 2, 2, 2, 2, 2};
__constant__ int c_foff[7] = {0, 8, 16, 32, 48, 64, 80};
__constant__ int c_roff[7] = {0, 1, 2, 4, 6, 8, 10};

__device__ float g_Q[BB * HH * SSL * DDIM];
__device__ float g_K[BB * HH * SSL * DDIM];
__device__ float g_V[BB * HH * SSL * DDIM];
__device__ float g_O[BB * HH * SSL * DDIM];

__device__ __forceinline__ float tf32r(float x) {
    uint32_t u;
    asm("cvt.rna.tf32.f32 %0, %1;" : "=r"(u) : "f"(x));
    return __uint_as_float(u);
}

__device__ __forceinline__ void mma_tf32(float* c, const uint32_t* a,
                                         uint32_t b0, uint32_t b1) {
    asm volatile(
        "mma.sync.aligned.m16n8k8.row.col.f32.tf32.tf32.f32 "
        "{%0,%1,%2,%3}, {%4,%5,%6,%7}, {%8,%9}, {%0,%1,%2,%3};"
        : "+f"(c[0]), "+f"(c[1]), "+f"(c[2]), "+f"(c[3])
        : "r"(a[0]), "r"(a[1]), "r"(a[2]), "r"(a[3]), "r"(b0), "r"(b1));
}

__device__ __forceinline__ void ldsm_x4(uint32_t& r0, uint32_t& r1,
                                        uint32_t& r2, uint32_t& r3, uint32_t addr) {
    asm volatile("ldmatrix.sync.aligned.m8n8.x4.shared.b16 {%0,%1,%2,%3}, [%4];"
        : "=r"(r0), "=r"(r1), "=r"(r2), "=r"(r3) : "r"(addr));
}

__device__ __forceinline__ uint32_t s2u(const void* p) {
    return (uint32_t)__cvta_generic_to_shared(p);
}
__device__ __forceinline__ void cp_async16(uint32_t saddr, const void* g) {
    asm volatile("cp.async.cg.shared.global [%0], [%1], 16;" :: "r"(saddr), "l"(g));
}
#define CP_COMMIT() asm volatile("cp.async.commit_group;")

// ---------------------------------------------------------------------------
// Kernel 1: FUSED QKV projection + head split, tf32 MMA, float4 staging
// (exact R15) grid (S/64, B, 7); smem ~87 KB
// ---------------------------------------------------------------------------
#define WPITCH 68
#define XPITCH 68
#define PROJ_SMEM_FLOATS (3 * 64 * WPITCH + 128 * XPITCH)

__global__ __launch_bounds__(256) void k_proj(
    const float* __restrict__ x0, const float* __restrict__ x1,
    const float* __restrict__ x2, const float* __restrict__ x3,
    const float* __restrict__ x4, const float* __restrict__ x5,
    const float* __restrict__ x6,
    const float* __restrict__ Wq, const float* __restrict__ Wk,
    const float* __restrict__ Wv)
{
    extern __shared__ float sm[];
    float* Ws = sm;                     // 3 x [64][68]
    float* xs = sm + 3 * 64 * WPITCH;   // [rows][68]

    const int key = blockIdx.z;
    const int b   = blockIdx.y;
    const int s0  = blockIdx.x * 64;
    const int d    = c_dim[key];
    const int rows = 64 * d;
    const int foff = c_foff[key];
    const int tid = threadIdx.x;

    const float* xg;
    switch (key) {
        case 0: xg = x0; break; case 1: xg = x1; break;
        case 2: xg = x2; break; case 3: xg = x3; break;
        case 4: xg = x4; break; case 5: xg = x5; break;
        default: xg = x6; break;
    }
    xg += (size_t)(b * SSL + s0) * d * 64;

    {
        const float4* w0 = (const float4*)(Wq + key * 4096);
        const float4* w1 = (const float4*)(Wk + key * 4096);
        const float4* w2 = (const float4*)(Wv + key * 4096);
        for (int i = tid; i < 1024; i += 256) {
            int o = i >> 4, k4 = (i & 15) * 4;
            float4 a = w0[i], bq = w1[i], c = w2[i];
            float* p0 = Ws + 0 * 64 * WPITCH + o * WPITCH + k4;
            float* p1 = Ws + 1 * 64 * WPITCH + o * WPITCH + k4;
            float* p2 = Ws + 2 * 64 * WPITCH + o * WPITCH + k4;
            p0[0]=tf32r(a.x);  p0[1]=tf32r(a.y);  p0[2]=tf32r(a.z);  p0[3]=tf32r(a.w);
            p1[0]=tf32r(bq.x); p1[1]=tf32r(bq.y); p1[2]=tf32r(bq.z); p1[3]=tf32r(bq.w);
            p2[0]=tf32r(c.x);  p2[1]=tf32r(c.y);  p2[2]=tf32r(c.z);  p2[3]=tf32r(c.w);
        }
        const float4* xg4 = (const float4*)xg;
        for (int i = tid; i < rows * 16; i += 256) {
            int r = i >> 4, k4 = (i & 15) * 4;
            float4 v = xg4[i];
            float* p = xs + r * XPITCH + k4;
            p[0]=tf32r(v.x); p[1]=tf32r(v.y); p[2]=tf32r(v.z); p[3]=tf32r(v.w);
        }
    }
    __syncthreads();

    const int wid  = tid >> 5;
    const int lane = tid & 31;
    const int gid  = lane >> 2;
    const int tig  = lane & 3;
    const int rbase = (wid & 3) * 16 * d;
    const int cbase = (wid >> 2) * 32;

    for (int m3 = 0; m3 < 3; m3++) {
        const float* Wm = Ws + m3 * 64 * WPITCH;

        float qacc[2][4][4];
        #pragma unroll
        for (int mf = 0; mf < 2; mf++)
            #pragma unroll
            for (int f = 0; f < 4; f++)
                #pragma unroll
                for (int c = 0; c < 4; c++) qacc[mf][f][c] = 0.0f;

        for (int k0 = 0; k0 < 64; k0 += 8) {
            uint32_t a[2][4];
            for (int mf = 0; mf < d; mf++) {
                const float* qb = xs + (rbase + mf * 16 + gid) * XPITCH + k0;
                a[mf][0] = __float_as_uint(qb[tig]);
                a[mf][1] = __float_as_uint(qb[8 * XPITCH + tig]);
                a[mf][2] = __float_as_uint(qb[tig + 4]);
                a[mf][3] = __float_as_uint(qb[8 * XPITCH + tig + 4]);
            }
            #pragma unroll
            for (int f = 0; f < 4; f++) {
                const float* kb = Wm + (cbase + f * 8 + gid) * WPITCH + k0;
                uint32_t b0 = __float_as_uint(kb[tig]);
                uint32_t b1 = __float_as_uint(kb[tig + 4]);
                mma_tf32(qacc[0][f], a[0], b0, b1);
                if (d == 2) mma_tf32(qacc[1][f], a[1], b0, b1);
            }
        }

        float* dst = (m3 == 0) ? g_Q : (m3 == 1) ? g_K : g_V;
        for (int mf = 0; mf < d; mf++) {
            int rlo = rbase + mf * 16 + gid;
            int rhi = rlo + 8;
            int sslo = rlo / d, ddlo = rlo - sslo * d;
            int sshi = rhi / d, ddhi = rhi - sshi * d;
            #pragma unroll
            for (int f = 0; f < 4; f++) {
                int col = cbase + f * 8;
                int h = col >> 3;
                float* plo = dst + (((size_t)(b * HH + h)) * SSL + s0 + sslo) * DDIM
                                 + foff + ddlo * 8 + tig * 2;
                float* phi = dst + (((size_t)(b * HH + h)) * SSL + s0 + sshi) * DDIM
                                 + foff + ddhi * 8 + tig * 2;
                plo[0] = tf32r(qacc[mf][f][0]); plo[1] = tf32r(qacc[mf][f][1]);
                phi[0] = tf32r(qacc[mf][f][2]); phi[1] = tf32r(qacc[mf][f][3]);
            }
        }
    }
}

// ---------------------------------------------------------------------------
// Kernel 2: flash attention, FULL-ROW WARPS (FA2-style register P)
// QT=128, 8 warps x 16 rows. QK: warp computes S[16][64] (8 n-frags).
// P repacked C-frag -> A-frag via quad shuffles; PV entirely in-warp.
// 2 barriers/tile. smem ~103 KB -> 2 blocks/SM.
// ---------------------------------------------------------------------------
#define QT 128
#define KT 64
#define NTILES (SSL / KT)
#define QPITCH 100
#define KPITCH 100
#define VPITCH 104

#define ATTN_SMEM_FLOATS (QT*QPITCH + KT*KPITCH + KT*VPITCH)

__global__ __launch_bounds__(256, 2) void k_attn()
{
    extern __shared__ float sm[];
    float* Qs = sm;                     // [128][100]
    float* Ks = Qs + QT * QPITCH;       // [64][100]
    float* Vs = Ks + KT * KPITCH;       // [64][104]

    const int bh = blockIdx.y;
    const int q0 = blockIdx.x * QT;
    const float* Qg = g_Q + ((size_t)bh * SSL + q0) * DDIM;
    const float* Kg = g_K + (size_t)bh * SSL * DDIM;
    const float* Vg = g_V + (size_t)bh * SSL * DDIM;

    const int tid  = threadIdx.x;
    const int wid  = tid >> 5;
    const int lane = tid & 31;
    const int gid  = lane >> 2;
    const int tig  = lane & 3;
    const int wbase = wid * 16;          // this warp's q-row base
    const float scale = 0.1020620726159658f;   // 1/sqrt(96)

    const int midx = lane >> 3, mrow = lane & 7;
    // Q A-frag x4: row wbase + (midx&1)*8 + mrow, col (midx>>1)*4
    const uint32_t qaddr =
        s2u(&Qs[(wbase + (midx & 1) * 8 + mrow) * QPITCH + (midx >> 1) * 4]);
    // K pair-x4: matrices 0,1 = n-frag 2np (cols k0/k0+4); 2,3 = n-frag 2np+1
    const uint32_t kaddr =
        s2u(&Ks[((midx >> 1) * 8 + mrow) * KPITCH + (midx & 1) * 4]);

    // stage Q (pre-rounded tf32 in g_Q)
    for (int i = tid; i < QT * (DDIM / 4); i += 256) {
        int r = i / (DDIM / 4), c4 = (i - r * (DDIM / 4)) * 4;
        *(float4*)&Qs[r * QPITCH + c4] = *(const float4*)(Qg + r * DDIM + c4);
    }

    float oacc[12][4];
    #pragma unroll
    for (int nf = 0; nf < 12; nf++)
        #pragma unroll
        for (int c = 0; c < 4; c++) oacc[nf][c] = 0.0f;

    float lsum0 = 0.0f, lsum1 = 0.0f;   // rows wbase+gid, wbase+gid+8

    const int srcA = (lane & ~3) | (tig >> 1);   // owner of col tig
    const int srcB = srcA + 2;                   // owner of col tig+4
    const bool oddt = (tig & 1) != 0;

    for (int t = 0; t < NTILES; t++) {
        __syncthreads();   // previous tile's K/V consumed by all warps

        {
            const float* Kt = Kg + (size_t)t * KT * DDIM;
            const float* Vt = Vg + (size_t)t * KT * DDIM;
            for (int i = tid; i < KT * (DDIM / 4); i += 256) {
                int r = i / (DDIM / 4), c4 = (i - r * (DDIM / 4)) * 4;
                cp_async16(s2u(Ks + r * KPITCH + c4), Kt + (size_t)r * DDIM + c4);
                cp_async16(s2u(Vs + r * VPITCH + c4), Vt + (size_t)r * DDIM + c4);
            }
            CP_COMMIT();
            asm volatile("cp.async.wait_group 0;");
        }
        __syncthreads();   // K/V visible

        // ---- S = Q K^T : warp computes S[16][64], 8 n-frags ----
        float qacc[8][4];
        #pragma unroll
        for (int f = 0; f < 8; f++)
            #pragma unroll
            for (int c = 0; c < 4; c++) qacc[f][c] = 0.0f;

        #pragma unroll
        for (int ks = 0; ks < DDIM / 8; ks++) {
            const int k0 = ks * 8;
            uint32_t a[4];
            ldsm_x4(a[0], a[1], a[2], a[3], qaddr + k0 * 4);
            #pragma unroll
            for (int np = 0; np < 4; np++) {
                uint32_t b0, b1, b2, b3;
                ldsm_x4(b0, b1, b2, b3,
                        kaddr + (uint32_t)(np * 16 * KPITCH + k0) * 4);
                mma_tf32(qacc[2 * np],     a, b0, b1);
                mma_tf32(qacc[2 * np + 1], a, b2, b3);
            }
        }

        // ---- P = exp(S*scale); row sums; repack C-frag -> A-frag in place ----
        #pragma unroll
        for (int f = 0; f < 8; f++) {
            float e0 = __expf(qacc[f][0] * scale);
            float e1 = __expf(qacc[f][1] * scale);
            float e2 = __expf(qacc[f][2] * scale);
            float e3 = __expf(qacc[f][3] * scale);
            lsum0 += e0 + e1;
            lsum1 += e2 + e3;
            e0 = tf32r(e0); e1 = tf32r(e1); e2 = tf32r(e2); e3 = tf32r(e3);
            // quad shuffle: cols {2t,2t+1} -> cols {t, t+4}
            float a0s = __shfl_sync(0xffffffffu, e0, srcA);
            float a1s = __shfl_sync(0xffffffffu, e1, srcA);
            float a2s = __shfl_sync(0xffffffffu, e2, srcA);
            float a3s = __shfl_sync(0xffffffffu, e3, srcA);
            float b0s = __shfl_sync(0xffffffffu, e0, srcB);
            float b1s = __shfl_sync(0xffffffffu, e1, srcB);
            float b2s = __shfl_sync(0xffffffffu, e2, srcB);
            float b3s = __shfl_sync(0xffffffffu, e3, srcB);
            qacc[f][0] = oddt ? a1s : a0s;   // row gid,   col 8f+tig
            qacc[f][1] = oddt ? a3s : a2s;   // row gid+8, col 8f+tig
            qacc[f][2] = oddt ? b1s : b0s;   // row gid,   col 8f+tig+4
            qacc[f][3] = oddt ? b3s : b2s;   // row gid+8, col 8f+tig+4
        }

        // ---- O += P V : in-warp, P from registers ----
        #pragma unroll
        for (int ks = 0; ks < 8; ks++) {
            const int k0 = ks * 8;
            uint32_t a[4] = {
                __float_as_uint(qacc[ks][0]), __float_as_uint(qacc[ks][1]),
                __float_as_uint(qacc[ks][2]), __float_as_uint(qacc[ks][3])
            };
            #pragma unroll
            for (int nf = 0; nf < 12; nf++) {
                int n = nf * 8 + gid;
                uint32_t b0 = __float_as_uint(Vs[(k0 + tig) * VPITCH + n]);
                uint32_t b1 = __float_as_uint(Vs[(k0 + tig + 4) * VPITCH + n]);
                mma_tf32(oacc[nf], a, b0, b1);
            }
        }
    }

    // ---- row sums: quad reduction; normalize + write ----
    lsum0 += __shfl_xor_sync(0xffffffffu, lsum0, 1);
    lsum0 += __shfl_xor_sync(0xffffffffu, lsum0, 2);
    lsum1 += __shfl_xor_sync(0xffffffffu, lsum1, 1);
    lsum1 += __shfl_xor_sync(0xffffffffu, lsum1, 2);
    const float i0 = 1.0f / lsum0;
    const float i1 = 1.0f / lsum1;

    {
        float* plo = g_O + ((size_t)bh * SSL + q0 + wbase + gid) * DDIM;
        float* phi = g_O + ((size_t)bh * SSL + q0 + wbase + gid + 8) * DDIM;
        #pragma unroll
        for (int nf = 0; nf < 12; nf++) {
            int col = nf * 8 + tig * 2;
            plo[col]     = oacc[nf][0] * i0;
            plo[col + 1] = oacc[nf][1] * i0;
            phi[col]     = oacc[nf][2] * i1;
            phi[col + 1] = oacc[nf][3] * i1;
        }
    }
}

// ---------------------------------------------------------------------------
// Kernel 3: combine heads + per-key Wo projection, tf32 MMA (exact R12)
// ---------------------------------------------------------------------------
#define OUT_SMEM_FLOATS (64 * WPITCH + 128 * XPITCH)

__global__ __launch_bounds__(256) void k_out(
    const float* __restrict__ Wo, float* __restrict__ out)
{
    extern __shared__ float sm[];
    float* Ws = sm;                 // [64][68]  Wo native [o][k]
    float* xs = sm + 64 * WPITCH;   // [rows][68] combined heads

    const int key = blockIdx.z;
    const int b   = blockIdx.y;
    const int s0  = blockIdx.x * 64;
    const int d    = c_dim[key];
    const int rows = 64 * d;
    const int foff = c_foff[key];
    const int roff = c_roff[key];
    const int tid = threadIdx.x;

    const float* w = Wo + key * 4096;
    for (int i = tid; i < 4096; i += 256) {
        int o = i >> 6, k = i & 63;
        Ws[o * WPITCH + k] = tf32r(w[i]);
    }
    for (int i = tid; i < rows * 64; i += 256) {
        int row = i >> 6, mp = i & 63;
        int ss = row / d, dd = row - ss * d;
        xs[row * XPITCH + mp] = tf32r(
            g_O[(((size_t)(b * HH + (mp >> 3))) * SSL + s0 + ss) * DDIM
                + foff + dd * 8 + (mp & 7)]);
    }
    __syncthreads();

    const int wid  = tid >> 5;
    const int lane = tid & 31;
    const int gid  = lane >> 2;
    const int tig  = lane & 3;
    const int rbase = (wid & 3) * 16 * d;
    const int cbase = (wid >> 2) * 32;

    float qacc[2][4][4];
    #pragma unroll
    for (int mf = 0; mf < 2; mf++)
        #pragma unroll
        for (int f = 0; f < 4; f++)
            #pragma unroll
            for (int c = 0; c < 4; c++) qacc[mf][f][c] = 0.0f;

    for (int k0 = 0; k0 < 64; k0 += 8) {
        uint32_t a[2][4];
        for (int mf = 0; mf < d; mf++) {
            const float* qb = xs + (rbase + mf * 16 + gid) * XPITCH + k0;
            a[mf][0] = __float_as_uint(qb[tig]);
            a[mf][1] = __float_as_uint(qb[8 * XPITCH + tig]);
            a[mf][2] = __float_as_uint(qb[tig + 4]);
            a[mf][3] = __float_as_uint(qb[8 * XPITCH + tig + 4]);
        }
        #pragma unroll
        for (int f = 0; f < 4; f++) {
            const float* kb = Ws + (cbase + f * 8 + gid) * WPITCH + k0;
            uint32_t b0 = __float_as_uint(kb[tig]);
            uint32_t b1 = __float_as_uint(kb[tig + 4]);
            mma_tf32(qacc[0][f], a[0], b0, b1);
            if (d == 2) mma_tf32(qacc[1][f], a[1], b0, b1);
        }
    }

    for (int mf = 0; mf < d; mf++) {
        int rlo = rbase + mf * 16 + gid;
        int rhi = rlo + 8;
        int sslo = rlo / d, ddlo = rlo - sslo * d;
        int sshi = rhi / d, ddhi = rhi - sshi * d;
        #pragma unroll
        for (int f = 0; f < 4; f++) {
            int col = cbase + f * 8 + tig * 2;
            float* plo = out + (((size_t)(b * SSL) + s0 + sslo) * 12 + roff + ddlo) * 64 + col;
            float* phi = out + (((size_t)(b * SSL) + s0 + sshi) * 12 + roff + ddhi) * 64 + col;
            plo[0] = qacc[mf][f][0]; plo[1] = qacc[mf][f][1];
            phi[0] = qacc[mf][f][2]; phi[1] = qacc[mf][f][3];
        }
    }
}

// ---------------------------------------------------------------------------
extern "C" void kernel_launch(void* const* d_in, const int* in_sizes, int n_in,
                              void* d_out, int out_size)
{
    const float* x0 = (const float*)d_in[0];
    const float* x1 = (const float*)d_in[1];
    const float* x2 = (const float*)d_in[2];
    const float* x3 = (const float*)d_in[3];
    const float* x4 = (const float*)d_in[4];
    const float* x5 = (const float*)d_in[5];
    const float* x6 = (const float*)d_in[6];
    const float* Wq = (const float*)d_in[7];
    const float* Wk = (const float*)d_in[8];
    const float* Wv = (const float*)d_in[9];
    const float* Wo = (const float*)d_in[10];
    float* out = (float*)d_out;

    const int proj_smem = PROJ_SMEM_FLOATS * 4;            // ~87 KB
    const int attn_smem = ATTN_SMEM_FLOATS * 4;            // ~103 KB -> 2 blocks/SM
    const int out_smem  = OUT_SMEM_FLOATS * 4;             // ~52 KB

    cudaFuncSetAttribute(k_proj, cudaFuncAttributeMaxDynamicSharedMemorySize, proj_smem);
    cudaFuncSetAttribute(k_attn, cudaFuncAttributeMaxDynamicSharedMemorySize, attn_smem);
    cudaFuncSetAttribute(k_out,  cudaFuncAttributeMaxDynamicSharedMemorySize, out_smem);

    k_proj<<<dim3(SSL / 64, BB, NKEY), 256, proj_smem>>>(
        x0, x1, x2, x3, x4, x5, x6, Wq, Wk, Wv);
    k_attn<<<dim3(SSL / QT, BB * HH), 256, attn_smem>>>();
    k_out<<<dim3(SSL / 64, BB, NKEY), 256, out_smem>>>(Wo, out);
}